// round 1
// baseline (speedup 1.0000x reference)
#include <cuda_runtime.h>

// Problem constants
#define TT 2048   // tokens (B*L)
#define DD 2048   // model dim
#define EE 8      // experts
#define HH 1408   // expert hidden
#define HSD 2816  // shared hidden

// GEMM tiling
#define BM 64
#define BN 64
#define BK 32

// ---------------- scratch (device globals; no runtime allocation) ------------
__device__ int   g_cnt[EE];
__device__ int   g_perm[EE * TT];
__device__ float g_cw[EE * TT];
__device__ float g_sgate[TT];
__device__ float g_h[(size_t)EE * TT * HH];    // per-expert gathered hidden (silu(g)*u)
__device__ float g_hs[(size_t)TT * HSD];       // shared-expert hidden

// ---------------- kernel 0: reset router counters -----------------------------
__global__ void zero_cnt_kernel() {
    if (threadIdx.x < EE) g_cnt[threadIdx.x] = 0;
}

// ---------------- kernel 1: router (logits -> softmax -> top2 -> lists) -------
// also computes shared-expert sigmoid gate
__global__ void __launch_bounds__(256) router_kernel(
    const float* __restrict__ x,
    const float* __restrict__ gate_w,
    const float* __restrict__ shgate_w)
{
    int t = blockIdx.x;
    const float* xr = x + (size_t)t * DD;
    float acc[9];
#pragma unroll
    for (int v = 0; v < 9; v++) acc[v] = 0.f;
    for (int j = threadIdx.x; j < DD; j += 256) {
        float xv = xr[j];
#pragma unroll
        for (int e = 0; e < EE; e++) acc[e] = fmaf(xv, gate_w[e * DD + j], acc[e]);
        acc[8] = fmaf(xv, shgate_w[j], acc[8]);
    }
#pragma unroll
    for (int o = 16; o > 0; o >>= 1) {
#pragma unroll
        for (int v = 0; v < 9; v++) acc[v] += __shfl_down_sync(0xffffffffu, acc[v], o);
    }
    __shared__ float sred[9][8];
    int lane = threadIdx.x & 31, wid = threadIdx.x >> 5;
    if (lane == 0) {
#pragma unroll
        for (int v = 0; v < 9; v++) sred[v][wid] = acc[v];
    }
    __syncthreads();
    if (threadIdx.x == 0) {
        float l[9];
#pragma unroll
        for (int v = 0; v < 9; v++) {
            float s = 0.f;
#pragma unroll
            for (int w = 0; w < 8; w++) s += sred[v][w];
            l[v] = s;
        }
        float m = l[0];
#pragma unroll
        for (int e = 1; e < EE; e++) m = fmaxf(m, l[e]);
        float p[EE];
#pragma unroll
        for (int e = 0; e < EE; e++) p[e] = expf(l[e] - m);
        // top-2 (lowest index wins ties, matching jax top_k)
        int i0 = 0;
#pragma unroll
        for (int e = 1; e < EE; e++) if (p[e] > p[i0]) i0 = e;
        int i1 = (i0 == 0) ? 1 : 0;
#pragma unroll
        for (int e = 0; e < EE; e++) if (e != i0 && p[e] > p[i1]) i1 = e;
        float inv = 1.f / (p[i0] + p[i1]);
        int q0 = atomicAdd(&g_cnt[i0], 1);
        g_perm[i0 * TT + q0] = t;
        g_cw[i0 * TT + q0]   = p[i0] * inv;
        int q1 = atomicAdd(&g_cnt[i1], 1);
        g_perm[i1 * TT + q1] = t;
        g_cw[i1 * TT + q1]   = p[i1] * inv;
        g_sgate[t] = 1.f / (1.f + expf(-l[8]));
    }
}

// ---------------- kernel 2: expert gate/up GEMM + SiLU*up ---------------------
// C[pos,h] = silu(xg @ Wg) * (xg @ Wu), rows gathered by router lists
__global__ void __launch_bounds__(256) expert_gateup_kernel(
    const float* __restrict__ x,
    const float* __restrict__ w_gate,
    const float* __restrict__ w_up)
{
    int e = blockIdx.z;
    int n = g_cnt[e];
    int row0 = blockIdx.y * BM;
    if (row0 >= n) return;
    int col0 = blockIdx.x * BN;

    __shared__ float As[BM][BK + 1];
    __shared__ float Bg[BK][BN];
    __shared__ float Bu[BK][BN];

    int tid = threadIdx.x;
    int tx = tid & 15, ty = tid >> 4;
    const float* wg = w_gate + (size_t)e * DD * HH;
    const float* wu = w_up   + (size_t)e * DD * HH;

    int tok[2];
#pragma unroll
    for (int i = 0; i < 2; i++) {
        int idx = tid + i * 256;
        int r = idx >> 3;
        int pos = row0 + r;
        tok[i] = (pos < n) ? g_perm[e * TT + pos] : g_perm[e * TT];
    }

    float ag[4][4], au[4][4];
#pragma unroll
    for (int a = 0; a < 4; a++)
#pragma unroll
        for (int b = 0; b < 4; b++) { ag[a][b] = 0.f; au[a][b] = 0.f; }

    for (int k0 = 0; k0 < DD; k0 += BK) {
#pragma unroll
        for (int i = 0; i < 2; i++) {
            int idx = tid + i * 256;
            int r = idx >> 3;
            int kk = (idx & 7) << 2;
            float4 v = *(const float4*)(x + (size_t)tok[i] * DD + k0 + kk);
            As[r][kk + 0] = v.x; As[r][kk + 1] = v.y;
            As[r][kk + 2] = v.z; As[r][kk + 3] = v.w;
        }
#pragma unroll
        for (int i = 0; i < 2; i++) {
            int idx = tid + i * 256;
            int kk = idx >> 4;
            int c = (idx & 15) << 2;
            size_t off = (size_t)(k0 + kk) * HH + col0 + c;
            *(float4*)&Bg[kk][c] = *(const float4*)(wg + off);
            *(float4*)&Bu[kk][c] = *(const float4*)(wu + off);
        }
        __syncthreads();
#pragma unroll
        for (int kk = 0; kk < BK; kk++) {
            float a[4];
#pragma unroll
            for (int tm = 0; tm < 4; tm++) a[tm] = As[ty * 4 + tm][kk];
            float4 bg4 = *(const float4*)&Bg[kk][tx * 4];
            float4 bu4 = *(const float4*)&Bu[kk][tx * 4];
            float bg[4] = {bg4.x, bg4.y, bg4.z, bg4.w};
            float bu[4] = {bu4.x, bu4.y, bu4.z, bu4.w};
#pragma unroll
            for (int tm = 0; tm < 4; tm++)
#pragma unroll
                for (int tn = 0; tn < 4; tn++) {
                    ag[tm][tn] = fmaf(a[tm], bg[tn], ag[tm][tn]);
                    au[tm][tn] = fmaf(a[tm], bu[tn], au[tm][tn]);
                }
        }
        __syncthreads();
    }
#pragma unroll
    for (int tm = 0; tm < 4; tm++) {
        int pos = row0 + ty * 4 + tm;
        if (pos < n) {
            float* o = g_h + ((size_t)e * TT + pos) * HH + col0 + tx * 4;
#pragma unroll
            for (int tn = 0; tn < 4; tn++) {
                float g = ag[tm][tn], u = au[tm][tn];
                o[tn] = u * (g / (1.f + expf(-g)));
            }
        }
    }
}

// ---------------- kernel 3: shared gate/up GEMM + SiLU*up ---------------------
__global__ void __launch_bounds__(256) shared_gateup_kernel(
    const float* __restrict__ x,
    const float* __restrict__ shw_gate,
    const float* __restrict__ shw_up)
{
    int row0 = blockIdx.y * BM;
    int col0 = blockIdx.x * BN;

    __shared__ float As[BM][BK + 1];
    __shared__ float Bg[BK][BN];
    __shared__ float Bu[BK][BN];

    int tid = threadIdx.x;
    int tx = tid & 15, ty = tid >> 4;

    float ag[4][4], au[4][4];
#pragma unroll
    for (int a = 0; a < 4; a++)
#pragma unroll
        for (int b = 0; b < 4; b++) { ag[a][b] = 0.f; au[a][b] = 0.f; }

    for (int k0 = 0; k0 < DD; k0 += BK) {
#pragma unroll
        for (int i = 0; i < 2; i++) {
            int idx = tid + i * 256;
            int r = idx >> 3;
            int kk = (idx & 7) << 2;
            float4 v = *(const float4*)(x + (size_t)(row0 + r) * DD + k0 + kk);
            As[r][kk + 0] = v.x; As[r][kk + 1] = v.y;
            As[r][kk + 2] = v.z; As[r][kk + 3] = v.w;
        }
#pragma unroll
        for (int i = 0; i < 2; i++) {
            int idx = tid + i * 256;
            int kk = idx >> 4;
            int c = (idx & 15) << 2;
            size_t off = (size_t)(k0 + kk) * HSD + col0 + c;
            *(float4*)&Bg[kk][c] = *(const float4*)(shw_gate + off);
            *(float4*)&Bu[kk][c] = *(const float4*)(shw_up + off);
        }
        __syncthreads();
#pragma unroll
        for (int kk = 0; kk < BK; kk++) {
            float a[4];
#pragma unroll
            for (int tm = 0; tm < 4; tm++) a[tm] = As[ty * 4 + tm][kk];
            float4 bg4 = *(const float4*)&Bg[kk][tx * 4];
            float4 bu4 = *(const float4*)&Bu[kk][tx * 4];
            float bg[4] = {bg4.x, bg4.y, bg4.z, bg4.w};
            float bu[4] = {bu4.x, bu4.y, bu4.z, bu4.w};
#pragma unroll
            for (int tm = 0; tm < 4; tm++)
#pragma unroll
                for (int tn = 0; tn < 4; tn++) {
                    ag[tm][tn] = fmaf(a[tm], bg[tn], ag[tm][tn]);
                    au[tm][tn] = fmaf(a[tm], bu[tn], au[tm][tn]);
                }
        }
        __syncthreads();
    }
#pragma unroll
    for (int tm = 0; tm < 4; tm++) {
        int trow = row0 + ty * 4 + tm;
        float* o = g_hs + (size_t)trow * HSD + col0 + tx * 4;
#pragma unroll
        for (int tn = 0; tn < 4; tn++) {
            float g = ag[tm][tn], u = au[tm][tn];
            o[tn] = u * (g / (1.f + expf(-g)));
        }
    }
}

// ---------------- kernel 4: shared down-proj (writes out = sgate * (hs@Wd)) ---
__global__ void __launch_bounds__(256) shared_down_kernel(
    const float* __restrict__ shw_down,
    float* __restrict__ out)
{
    int row0 = blockIdx.y * BM;
    int col0 = blockIdx.x * BN;

    __shared__ float As[BM][BK + 1];
    __shared__ float Bs[BK][BN];

    int tid = threadIdx.x;
    int tx = tid & 15, ty = tid >> 4;

    float acc[4][4];
#pragma unroll
    for (int a = 0; a < 4; a++)
#pragma unroll
        for (int b = 0; b < 4; b++) acc[a][b] = 0.f;

    for (int k0 = 0; k0 < HSD; k0 += BK) {
#pragma unroll
        for (int i = 0; i < 2; i++) {
            int idx = tid + i * 256;
            int r = idx >> 3;
            int kk = (idx & 7) << 2;
            float4 v = *(const float4*)(g_hs + (size_t)(row0 + r) * HSD + k0 + kk);
            As[r][kk + 0] = v.x; As[r][kk + 1] = v.y;
            As[r][kk + 2] = v.z; As[r][kk + 3] = v.w;
        }
#pragma unroll
        for (int i = 0; i < 2; i++) {
            int idx = tid + i * 256;
            int kk = idx >> 4;
            int c = (idx & 15) << 2;
            *(float4*)&Bs[kk][c] = *(const float4*)(shw_down + (size_t)(k0 + kk) * DD + col0 + c);
        }
        __syncthreads();
#pragma unroll
        for (int kk = 0; kk < BK; kk++) {
            float a[4];
#pragma unroll
            for (int tm = 0; tm < 4; tm++) a[tm] = As[ty * 4 + tm][kk];
            float4 b4 = *(const float4*)&Bs[kk][tx * 4];
            float b[4] = {b4.x, b4.y, b4.z, b4.w};
#pragma unroll
            for (int tm = 0; tm < 4; tm++)
#pragma unroll
                for (int tn = 0; tn < 4; tn++)
                    acc[tm][tn] = fmaf(a[tm], b[tn], acc[tm][tn]);
        }
        __syncthreads();
    }
#pragma unroll
    for (int tm = 0; tm < 4; tm++) {
        int trow = row0 + ty * 4 + tm;
        float sg = g_sgate[trow];
        float4 v;
        v.x = sg * acc[tm][0]; v.y = sg * acc[tm][1];
        v.z = sg * acc[tm][2]; v.w = sg * acc[tm][3];
        *(float4*)(out + (size_t)trow * DD + col0 + tx * 4) = v;
    }
}

// ---------------- kernel 5: expert down-proj (atomicAdd into out) -------------
__global__ void __launch_bounds__(256) expert_down_kernel(
    const float* __restrict__ w_down,
    float* __restrict__ out)
{
    int e = blockIdx.z;
    int n = g_cnt[e];
    int row0 = blockIdx.y * BM;
    if (row0 >= n) return;
    int col0 = blockIdx.x * BN;

    __shared__ float As[BM][BK + 1];
    __shared__ float Bs[BK][BN];

    int tid = threadIdx.x;
    int tx = tid & 15, ty = tid >> 4;
    const float* wd = w_down + (size_t)e * HH * DD;
    const float* Abase = g_h + ((size_t)e * TT + row0) * HH;

    float acc[4][4];
#pragma unroll
    for (int a = 0; a < 4; a++)
#pragma unroll
        for (int b = 0; b < 4; b++) acc[a][b] = 0.f;

    for (int k0 = 0; k0 < HH; k0 += BK) {
#pragma unroll
        for (int i = 0; i < 2; i++) {
            int idx = tid + i * 256;
            int r = idx >> 3;
            int kk = (idx & 7) << 2;
            float4 v = *(const float4*)(Abase + (size_t)r * HH + k0 + kk);
            As[r][kk + 0] = v.x; As[r][kk + 1] = v.y;
            As[r][kk + 2] = v.z; As[r][kk + 3] = v.w;
        }
#pragma unroll
        for (int i = 0; i < 2; i++) {
            int idx = tid + i * 256;
            int kk = idx >> 4;
            int c = (idx & 15) << 2;
            *(float4*)&Bs[kk][c] = *(const float4*)(wd + (size_t)(k0 + kk) * DD + col0 + c);
        }
        __syncthreads();
#pragma unroll
        for (int kk = 0; kk < BK; kk++) {
            float a[4];
#pragma unroll
            for (int tm = 0; tm < 4; tm++) a[tm] = As[ty * 4 + tm][kk];
            float4 b4 = *(const float4*)&Bs[kk][tx * 4];
            float b[4] = {b4.x, b4.y, b4.z, b4.w};
#pragma unroll
            for (int tm = 0; tm < 4; tm++)
#pragma unroll
                for (int tn = 0; tn < 4; tn++)
                    acc[tm][tn] = fmaf(a[tm], b[tn], acc[tm][tn]);
        }
        __syncthreads();
    }
#pragma unroll
    for (int tm = 0; tm < 4; tm++) {
        int pos = row0 + ty * 4 + tm;
        if (pos < n) {
            int t = g_perm[e * TT + pos];
            float cw = g_cw[e * TT + pos];
            float* o = out + (size_t)t * DD + col0 + tx * 4;
#pragma unroll
            for (int tn = 0; tn < 4; tn++)
                atomicAdd(&o[tn], cw * acc[tm][tn]);
        }
    }
}

// ---------------- launch --------------------------------------------------------
extern "C" void kernel_launch(void* const* d_in, const int* in_sizes, int n_in,
                              void* d_out, int out_size)
{
    const float* x        = (const float*)d_in[0];
    const float* gate_w   = (const float*)d_in[1];
    const float* w_gate   = (const float*)d_in[2];
    const float* w_up     = (const float*)d_in[3];
    const float* w_down   = (const float*)d_in[4];
    const float* shgate_w = (const float*)d_in[5];
    const float* shw_gate = (const float*)d_in[6];
    const float* shw_up   = (const float*)d_in[7];
    const float* shw_down = (const float*)d_in[8];
    float* out = (float*)d_out;

    zero_cnt_kernel<<<1, 32>>>();
    router_kernel<<<TT, 256>>>(x, gate_w, shgate_w);
    expert_gateup_kernel<<<dim3(HH / BN, TT / BM, EE), 256>>>(x, w_gate, w_up);
    shared_gateup_kernel<<<dim3(HSD / BN, TT / BM), 256>>>(x, shw_gate, shw_up);
    shared_down_kernel<<<dim3(DD / BN, TT / BM), 256>>>(shw_down, out);
    expert_down_kernel<<<dim3(DD / BN, TT / BM, EE), 256>>>(w_down, out);
}